// round 6
// baseline (speedup 1.0000x reference)
#include <cuda_runtime.h>
#include <math.h>

#define BB 16
#define SS 1024
#define DD 1024
#define HH 16
#define DH 64

// Scratch for Q, K, V in head-split layout [B, H, S, Dh] (64 MB each).
__device__ float g_q[BB * HH * SS * DH];
__device__ float g_k[BB * HH * SS * DH];
__device__ float g_v[BB * HH * SS * DH];

// ---------------------------------------------------------------------------
__device__ __forceinline__ float to_tf32(float x) {
    float r;
    asm("cvt.rna.tf32.f32 %0, %1;" : "=f"(r) : "f"(x));
    return r;
}

__device__ __forceinline__ void mma_tf32(float* d, const unsigned* a, const unsigned* b) {
    asm volatile(
        "mma.sync.aligned.m16n8k8.row.col.f32.tf32.tf32.f32 "
        "{%0,%1,%2,%3},{%4,%5,%6,%7},{%8,%9},{%0,%1,%2,%3};"
        : "+f"(d[0]), "+f"(d[1]), "+f"(d[2]), "+f"(d[3])
        : "r"(a[0]), "r"(a[1]), "r"(a[2]), "r"(a[3]), "r"(b[0]), "r"(b[1]));
}

// ---------------------------------------------------------------------------
// QKV projection, software-pipelined: Y = X @ W^T + b, head-split store.
// BM=BN=128, BK=16, 256 threads (8 warps as 4x2), warp tile 32x64.
// Per k-iter: STS(prefetched regs) -> sync -> LDG next tile -> mma (overlap).
// ---------------------------------------------------------------------------
__global__ __launch_bounds__(256)
void qkv_gemm(const float* __restrict__ X, const float* __restrict__ W,
              const float* __restrict__ bias, int which)
{
    __shared__ float sa[128][20];   // [m][k], stride 20 (frag LDS conflict-free)
    __shared__ float sb[128][20];   // [n][k]

    float* __restrict__ Y = (which == 0) ? g_q : (which == 1) ? g_k : g_v;

    const int tid  = threadIdx.x;
    const int lane = tid & 31;
    const int warp = tid >> 5;
    const int wm   = (warp & 3) * 32;
    const int wn   = (warp >> 2) * 64;
    const int m0   = blockIdx.y * 128;
    const int n0   = blockIdx.x * 128;

    // gmem/smem map: thread t -> row = t>>1 (0..127), col base = (t&1)*8.
    // Each thread moves two float4 per side per iter (cols cb..cb+3, cb+4..cb+7).
    const int lrow = tid >> 1;
    const int lcb  = (tid & 1) * 8;
    const float* srcA = X + (size_t)(m0 + lrow) * DD + lcb;
    const float* srcB = W + (size_t)(n0 + lrow) * DD + lcb;

    const int r4 = lane >> 2;
    const int c4 = lane & 3;

    float acc[2][8][4];
    #pragma unroll
    for (int i = 0; i < 2; i++)
        #pragma unroll
        for (int j = 0; j < 8; j++)
            #pragma unroll
            for (int c = 0; c < 4; c++) acc[i][j][c] = 0.0f;

    // prefetch k-tile 0
    float4 va0 = *(const float4*)(srcA);
    float4 va1 = *(const float4*)(srcA + 4);
    float4 vb0 = *(const float4*)(srcB);
    float4 vb1 = *(const float4*)(srcB + 4);

    for (int kt = 0; kt < 64; kt++) {
        __syncthreads();   // previous iteration's mma done reading smem
        sa[lrow][lcb + 0] = to_tf32(va0.x); sa[lrow][lcb + 1] = to_tf32(va0.y);
        sa[lrow][lcb + 2] = to_tf32(va0.z); sa[lrow][lcb + 3] = to_tf32(va0.w);
        sa[lrow][lcb + 4] = to_tf32(va1.x); sa[lrow][lcb + 5] = to_tf32(va1.y);
        sa[lrow][lcb + 6] = to_tf32(va1.z); sa[lrow][lcb + 7] = to_tf32(va1.w);
        sb[lrow][lcb + 0] = to_tf32(vb0.x); sb[lrow][lcb + 1] = to_tf32(vb0.y);
        sb[lrow][lcb + 2] = to_tf32(vb0.z); sb[lrow][lcb + 3] = to_tf32(vb0.w);
        sb[lrow][lcb + 4] = to_tf32(vb1.x); sb[lrow][lcb + 5] = to_tf32(vb1.y);
        sb[lrow][lcb + 6] = to_tf32(vb1.z); sb[lrow][lcb + 7] = to_tf32(vb1.w);
        __syncthreads();

        // issue next tile's loads BEFORE the mma section (latency overlap)
        if (kt < 63) {
            const int k0 = (kt + 1) * 16;
            va0 = *(const float4*)(srcA + k0);
            va1 = *(const float4*)(srcA + k0 + 4);
            vb0 = *(const float4*)(srcB + k0);
            vb1 = *(const float4*)(srcB + k0 + 4);
        }

        #pragma unroll
        for (int ks = 0; ks < 2; ks++) {
            const int kk = ks * 8;
            unsigned af[2][4];
            #pragma unroll
            for (int mt = 0; mt < 2; mt++) {
                const int rb = wm + mt * 16;
                af[mt][0] = __float_as_uint(sa[rb + r4    ][kk + c4    ]);
                af[mt][1] = __float_as_uint(sa[rb + r4 + 8][kk + c4    ]);
                af[mt][2] = __float_as_uint(sa[rb + r4    ][kk + c4 + 4]);
                af[mt][3] = __float_as_uint(sa[rb + r4 + 8][kk + c4 + 4]);
            }
            #pragma unroll
            for (int nt = 0; nt < 8; nt++) {
                const int cb = wn + nt * 8;
                unsigned bf[2];
                bf[0] = __float_as_uint(sb[cb + r4][kk + c4    ]);
                bf[1] = __float_as_uint(sb[cb + r4][kk + c4 + 4]);
                mma_tf32(acc[0][nt], af[0], bf);
                mma_tf32(acc[1][nt], af[1], bf);
            }
        }
    }

    // Epilogue: bias + head-split scatter (identical to R2).
    #pragma unroll
    for (int mt = 0; mt < 2; mt++) {
        const int mA = m0 + wm + mt * 16 + r4;
        const int mB = mA + 8;
        const int bA = mA >> 10, sA_ = mA & 1023;
        const int bB = mB >> 10, sB_ = mB & 1023;
        #pragma unroll
        for (int nt = 0; nt < 8; nt++) {
            const int col = n0 + wn + nt * 8 + 2 * c4;
            const int h = col >> 6, d = col & 63;
            const float b0 = bias[col], b1 = bias[col + 1];
            float2 vA = make_float2(acc[mt][nt][0] + b0, acc[mt][nt][1] + b1);
            float2 vB = make_float2(acc[mt][nt][2] + b0, acc[mt][nt][3] + b1);
            *(float2*)(Y + (((size_t)(bA * HH + h) * SS + sA_) * DH) + d) = vA;
            *(float2*)(Y + (((size_t)(bB * HH + h) * SS + sB_) * DH) + d) = vB;
        }
    }
}

// ---------------------------------------------------------------------------
// Flash attention with tf32 mma — byte-identical to R2 (measured 566us).
// Block: 128 thr (4 warps), BR=64 (16 q rows per warp), BC=32, Dh=64.
// ---------------------------------------------------------------------------
__global__ __launch_bounds__(128)
void attn_kernel(float* __restrict__ out)
{
    __shared__ float sk[32][68];        // [kv][dh]
    __shared__ float sv[32][72];        // [kv][dh]
    __shared__ float sp[4][16][68];     // per-warp: Q staging, then P tile

    const int tid  = threadIdx.x;
    const int lane = tid & 31;
    const int warp = tid >> 5;
    const int bh   = blockIdx.y;
    const int b    = bh >> 4;
    const int h    = bh & 15;
    const int qrow0 = blockIdx.x * 64 + warp * 16;   // warp's first q row

    const int r4 = lane >> 2;   // 0..7
    const int c4 = lane & 3;    // 0..3

    const float* Qb = g_q + (size_t)bh * SS * DH;
    const float* Kb = g_k + (size_t)bh * SS * DH;
    const float* Vb = g_v + (size_t)bh * SS * DH;

    // --- stage Q (scaled by 1/8, tf32-rounded) into sp[warp], load fragments
    {
        #pragma unroll
        for (int i = 0; i < 8; i++) {
            const int idx = lane + i * 32;          // 0..255
            const int row = idx >> 4;               // 0..15
            const int cc  = (idx & 15) * 4;
            float4 t = *(const float4*)(Qb + (size_t)(qrow0 + row) * DH + cc);
            sp[warp][row][cc + 0] = to_tf32(t.x * 0.125f);
            sp[warp][row][cc + 1] = to_tf32(t.y * 0.125f);
            sp[warp][row][cc + 2] = to_tf32(t.z * 0.125f);
            sp[warp][row][cc + 3] = to_tf32(t.w * 0.125f);
        }
    }
    __syncwarp();
    unsigned qa[8][4];
    #pragma unroll
    for (int kt = 0; kt < 8; kt++) {
        qa[kt][0] = __float_as_uint(sp[warp][r4    ][kt * 8 + c4    ]);
        qa[kt][1] = __float_as_uint(sp[warp][r4 + 8][kt * 8 + c4    ]);
        qa[kt][2] = __float_as_uint(sp[warp][r4    ][kt * 8 + c4 + 4]);
        qa[kt][3] = __float_as_uint(sp[warp][r4 + 8][kt * 8 + c4 + 4]);
    }
    __syncwarp();

    float o[8][4];
    #pragma unroll
    for (int nt = 0; nt < 8; nt++)
        #pragma unroll
        for (int c = 0; c < 4; c++) o[nt][c] = 0.0f;
    float m0v = -INFINITY, m1v = -INFINITY;
    float l0 = 0.0f, l1 = 0.0f;

    for (int t0 = 0; t0 < SS; t0 += 32) {
        __syncthreads();
        // cooperative load K,V tile (tf32-rounded): 32 rows x 16 float4
        #pragma unroll
        for (int i = 0; i < 4; i++) {
            const int idx = tid + i * 128;          // 0..511
            const int row = idx >> 4;               // 0..31
            const int cc  = (idx & 15) * 4;
            float4 kt4 = *(const float4*)(Kb + (size_t)(t0 + row) * DH + cc);
            float4 vt4 = *(const float4*)(Vb + (size_t)(t0 + row) * DH + cc);
            sk[row][cc + 0] = to_tf32(kt4.x); sk[row][cc + 1] = to_tf32(kt4.y);
            sk[row][cc + 2] = to_tf32(kt4.z); sk[row][cc + 3] = to_tf32(kt4.w);
            sv[row][cc + 0] = to_tf32(vt4.x); sv[row][cc + 1] = to_tf32(vt4.y);
            sv[row][cc + 2] = to_tf32(vt4.z); sv[row][cc + 3] = to_tf32(vt4.w);
        }
        __syncthreads();

        // S = Q @ K^T  : 4 n-tiles (kv) x 8 k-steps (dh)
        float s[4][4];
        #pragma unroll
        for (int nt = 0; nt < 4; nt++) {
            #pragma unroll
            for (int c = 0; c < 4; c++) s[nt][c] = 0.0f;
            #pragma unroll
            for (int kt = 0; kt < 8; kt++) {
                unsigned bf[2];
                bf[0] = __float_as_uint(sk[nt * 8 + r4][kt * 8 + c4    ]);
                bf[1] = __float_as_uint(sk[nt * 8 + r4][kt * 8 + c4 + 4]);
                mma_tf32(s[nt], qa[kt], bf);
            }
        }

        // online softmax (rows r4 and r4+8 within the warp tile)
        float tm0 = -INFINITY, tm1 = -INFINITY;
        #pragma unroll
        for (int nt = 0; nt < 4; nt++) {
            tm0 = fmaxf(tm0, fmaxf(s[nt][0], s[nt][1]));
            tm1 = fmaxf(tm1, fmaxf(s[nt][2], s[nt][3]));
        }
        tm0 = fmaxf(tm0, __shfl_xor_sync(0xffffffffu, tm0, 1));
        tm0 = fmaxf(tm0, __shfl_xor_sync(0xffffffffu, tm0, 2));
        tm1 = fmaxf(tm1, __shfl_xor_sync(0xffffffffu, tm1, 1));
        tm1 = fmaxf(tm1, __shfl_xor_sync(0xffffffffu, tm1, 2));

        const float mn0 = fmaxf(m0v, tm0);
        const float mn1 = fmaxf(m1v, tm1);
        const float sc0 = __expf(m0v - mn0);
        const float sc1 = __expf(m1v - mn1);
        m0v = mn0; m1v = mn1;

        float ps0 = 0.0f, ps1 = 0.0f;
        #pragma unroll
        for (int nt = 0; nt < 4; nt++) {
            s[nt][0] = __expf(s[nt][0] - mn0);
            s[nt][1] = __expf(s[nt][1] - mn0);
            s[nt][2] = __expf(s[nt][2] - mn1);
            s[nt][3] = __expf(s[nt][3] - mn1);
            ps0 += s[nt][0] + s[nt][1];
            ps1 += s[nt][2] + s[nt][3];
        }
        ps0 += __shfl_xor_sync(0xffffffffu, ps0, 1);
        ps0 += __shfl_xor_sync(0xffffffffu, ps0, 2);
        ps1 += __shfl_xor_sync(0xffffffffu, ps1, 1);
        ps1 += __shfl_xor_sync(0xffffffffu, ps1, 2);
        l0 = l0 * sc0 + ps0;
        l1 = l1 * sc1 + ps1;

        #pragma unroll
        for (int nt = 0; nt < 8; nt++) {
            o[nt][0] *= sc0; o[nt][1] *= sc0;
            o[nt][2] *= sc1; o[nt][3] *= sc1;
        }

        // write P to warp-private smem (tf32 rounded), reload as A fragments
        #pragma unroll
        for (int nt = 0; nt < 4; nt++) {
            float2 pA = make_float2(to_tf32(s[nt][0]), to_tf32(s[nt][1]));
            float2 pB = make_float2(to_tf32(s[nt][2]), to_tf32(s[nt][3]));
            *(float2*)&sp[warp][r4    ][nt * 8 + 2 * c4] = pA;
            *(float2*)&sp[warp][r4 + 8][nt * 8 + 2 * c4] = pB;
        }
        __syncwarp();

        // O += P @ V : 4 k-steps (kv) x 8 n-tiles (dh)
        unsigned pa[4][4];
        #pragma unroll
        for (int kt = 0; kt < 4; kt++) {
            pa[kt][0] = __float_as_uint(sp[warp][r4    ][kt * 8 + c4    ]);
            pa[kt][1] = __float_as_uint(sp[warp][r4 + 8][kt * 8 + c4    ]);
            pa[kt][2] = __float_as_uint(sp[warp][r4    ][kt * 8 + c4 + 4]);
            pa[kt][3] = __float_as_uint(sp[warp][r4 + 8][kt * 8 + c4 + 4]);
        }
        #pragma unroll
        for (int nt = 0; nt < 8; nt++) {
            #pragma unroll
            for (int kt = 0; kt < 4; kt++) {
                unsigned bf[2];
                bf[0] = __float_as_uint(sv[kt * 8 + c4    ][nt * 8 + r4]);
                bf[1] = __float_as_uint(sv[kt * 8 + c4 + 4][nt * 8 + r4]);
                mma_tf32(o[nt], pa[kt], bf);
            }
        }
        __syncwarp();
    }

    // epilogue: normalize and store (out[(b*S + s)*D + h*64 + d])
    const float inv0 = 1.0f / l0;
    const float inv1 = 1.0f / l1;
    const int rA = qrow0 + r4;
    const int rB = rA + 8;
    float* oA = out + ((size_t)(b * SS + rA)) * DD + h * DH;
    float* oB = out + ((size_t)(b * SS + rB)) * DD + h * DH;
    #pragma unroll
    for (int nt = 0; nt < 8; nt++) {
        const int d = nt * 8 + 2 * c4;
        *(float2*)(oA + d) = make_float2(o[nt][0] * inv0, o[nt][1] * inv0);
        *(float2*)(oB + d) = make_float2(o[nt][2] * inv1, o[nt][3] * inv1);
    }
}

extern "C" void kernel_launch(void* const* d_in, const int* in_sizes, int n_in,
                              void* d_out, int out_size)
{
    const float* x  = (const float*)d_in[0];
    const float* Wq = (const float*)d_in[1];
    const float* bq = (const float*)d_in[2];
    const float* Wk = (const float*)d_in[3];
    const float* bk = (const float*)d_in[4];
    const float* Wv = (const float*)d_in[5];
    const float* bv = (const float*)d_in[6];
    float* out = (float*)d_out;

    dim3 gg(DD / 128, (BB * SS) / 128);   // (8, 128)
    qkv_gemm<<<gg, 256>>>(x, Wq, bq, 0);
    qkv_gemm<<<gg, 256>>>(x, Wk, bk, 1);
    qkv_gemm<<<gg, 256>>>(x, Wv, bv, 2);

    dim3 ga(SS / 64, BB * HH);            // (16, 256)
    attn_kernel<<<ga, 128>>>(out);
}